// round 10
// baseline (speedup 1.0000x reference)
#include <cuda_runtime.h>
#include <math.h>

#define Bb      128
#define Ll      2048
#define NOBS    32
#define NHID    512
#define NSTEPS  (Ll - 1)          // 2047
#define NCTA    64                // 16 n-tiles x 4 m-tiles
#define NTHREADS 256              // 2 engines x 128 threads
#define NBARS   (NSTEPS - 1)
typedef unsigned long long u64;
#define GRP_CTAS 16               // CTAs per (m-tile, engine) group
#define BARMOD  ((u64)NBARS * GRP_CTAS)

// SMEM: A interleaved [256 k2][16 cp][4 floats] + 2 x X pair-major [8][514] u64
#define SA2_FLOATS (256 * 16 * 4)               // 65536 B
#define SX_STRIDE  514                          // u64 rows (16B-aligned)
#define SX_U64     (8 * SX_STRIDE)
#define SMEM_BYTES (SA2_FLOATS * 4 + 2 * SX_U64 * 8)  // 65536 + 65792 = 131328 B

// per-(m-tile, engine) barrier counters, one 128B line each
__device__ u64 g_counts[4][2][16];

// ---------------------------------------------------------------------------
__device__ __forceinline__ u64 pack2(float a, float b) {
    u64 r;
    asm("mov.b64 %0, {%1, %2};" : "=l"(r) : "f"(a), "f"(b));
    return r;
}
__device__ __forceinline__ void unpack2(u64 v, float& a, float& b) {
    asm("mov.b64 {%0, %1}, %2;" : "=f"(a), "=f"(b) : "l"(v));
}
__device__ __forceinline__ void ffma2(u64& acc, u64 a, u64 x) {
    asm("fma.rn.f32x2 %0, %1, %2, %0;" : "+l"(acc) : "l"(a), "l"(x));
}

// XLA EmitFastTanh (fma path) — verified bit-exact (rel_err 0.0). DO NOT CHANGE.
__device__ __forceinline__ float tanh_xla(float x) {
    const float kClamp = 7.99881172180175781f;
    float xc = fminf(fmaxf(x, -kClamp), kClamp);
    float x2 = __fmul_rn(xc, xc);
    float num = -2.76076847742355e-16f;
    num = fmaf(x2, num, 2.00018790482477e-13f);
    num = fmaf(x2, num, -8.60467152213735e-11f);
    num = fmaf(x2, num, 5.12229709037114e-08f);
    num = fmaf(x2, num, 1.48572235717979e-05f);
    num = fmaf(x2, num, 6.37261928875436e-04f);
    num = fmaf(x2, num, 4.89352455891786e-03f);
    num = __fmul_rn(xc, num);
    float den = 1.19825839466702e-06f;
    den = fmaf(x2, den, 1.18534705686654e-04f);
    den = fmaf(x2, den, 2.26843463243900e-03f);
    den = fmaf(x2, den, 4.89352518554385e-03f);
    float r = __fdiv_rn(num, den);
    return (fabsf(x) < 0.0004f) ? x : r;
}

// engine barrier: named bar + release-arrive + acquire-poll, engine-scoped
__device__ __forceinline__ void engine_barrier(int eng, int lt, u64* ctr, u64 target) {
    asm volatile("bar.sync %0, 128;" :: "r"(1 + eng) : "memory");
    if (lt == 0) {
        asm volatile("red.global.release.gpu.add.u64 [%0], %1;"
                     :: "l"(ctr), "n"(1ULL) : "memory");
        u64 v;
        do {
            asm volatile("ld.global.acquire.gpu.u64 %0, [%1];"
                         : "=l"(v) : "l"(ctr));
        } while (v < target);
    }
    asm volatile("bar.sync %0, 128;" :: "r"(1 + eng) : "memory");
}

// ---------------------------------------------------------------------------
// Persistent HCNN scan, order-exact fp32, dual-engine latency hiding.
// 64 CTAs = 16 n-tiles (32 cols) x 4 m-tiles (32 batches).
// 256 threads = 2 engines x 128 threads. Engine e (warps 4e..4e+3, one warp
// per SMSP interleaved with the other engine's) runs an independent 16-batch
// recurrence: own sx buffer, own 16-CTA group barrier, named-bar sync.
// Compute per engine identical to R8: thread tile = 1 pair x 2 cols,
// full ascending-k f32x2 chains (bit-exact).
// ---------------------------------------------------------------------------
__global__ void __launch_bounds__(NTHREADS, 1) ptf_persistent(
    const float* __restrict__ data,   // [B, L, NOBS]
    const float* __restrict__ Amat,   // [NHID, NHID]
    const float* __restrict__ h0,     // [NHID]
    float* __restrict__ exps,
    float* __restrict__ states,       // doubles as the recurrent state
    float* __restrict__ deltas,
    float* __restrict__ partials)
{
    extern __shared__ char smem_raw[];
    float* sA2 = (float*)smem_raw;                        // [256][16][4]
    u64*   sxb = (u64*)(smem_raw + SA2_FLOATS * 4);       // [2][8][514]

    const int tid = threadIdx.x;
    const int e   = tid >> 7;                 // engine 0/1
    const int lt  = tid & 127;                // thread id within engine
    const int lw  = lt >> 5;                  // engine-local warp 0..3
    const int l   = lt & 31;
    const int nt  = blockIdx.x & 15;
    const int mt  = blockIdx.x >> 4;          // 0..3
    const int n0  = nt * 32;
    const int m0  = mt * 32 + e * 16;         // engine's 16-batch base
    u64* ctr = &g_counts[mt][e][0];
    u64* sx  = sxb + (size_t)e * SX_U64;

    // ---- barrier base (monotonic counter across graph replays) ----
    u64 base;
    {
        u64 v;
        asm volatile("ld.global.acquire.gpu.u64 %0, [%1];" : "=l"(v) : "l"(ctr));
        base = v - (v % BARMOD);
    }

    // ---- one-time: A -> sA2[k2][cp][4] = {a_n[2k2], a_n[2k2+1],
    //                                       a_n1[2k2], a_n1[2k2+1]} ----
    for (int i = tid; i < 256 * 16; i += NTHREADS) {
        const int k2 = i >> 4;           // 0..255
        const int cp = i & 15;           // 0..15
        const int n  = n0 + 2 * cp;
        float2 a0 = *(const float2*)&Amat[(size_t)n * NHID + 2 * k2];
        float2 a1 = *(const float2*)&Amat[(size_t)(n + 1) * NHID + 2 * k2];
        float4 v  = make_float4(a0.x, a0.y, a1.x, a1.y);
        *(float4*)&sA2[(size_t)i * 4] = v;
    }
    __syncthreads();    // last full-CTA sync; engines diverge after this

    // compute-thread identifiers (within engine)
    const int p   = lt & 7;                   // pair 0..7
    const int cp  = lt >> 3;                  // col-pair 0..15
    const int nA  = n0 + 2 * cp;              // cols nA, nA+1
    const int bA  = m0 + p;                   // batches bA, bA+8
    const int bB  = bA + 8;
    const u64* xr = sx + (size_t)p * SX_STRIDE;

    for (int t = 0; t < NSTEPS; t++) {
        // ---------------- stage state pairs (+ exact injection + outputs) ----
        // engine warp lw stages pairs lw and lw+4; 4 float4-chunks per pair
        #pragma unroll
        for (int r = 0; r < 2; r++) {
            const int sp  = lw + 4 * r;
            const int sbA = m0 + sp;
            const int sbB = sbA + 8;
            #pragma unroll
            for (int j = 0; j < 4; j++) {
                const int k0 = 4 * l + 128 * j;
                const float* srcA = (t == 0) ? (h0 + k0)
                                  : (states + ((size_t)sbA * Ll + t) * NHID + k0);
                const float* srcB = (t == 0) ? (h0 + k0)
                                  : (states + ((size_t)sbB * Ll + t) * NHID + k0);
                float4 a4 = *(const float4*)srcA;
                float4 b4 = *(const float4*)srcB;

                if (t == 0 && nt == 0) {      // states[:,0,:] = s0 (pre-inject)
                    *(float4*)&states[((size_t)sbA * Ll) * NHID + k0] = a4;
                    *(float4*)&states[((size_t)sbB * Ll) * NHID + k0] = b4;
                }
                if (k0 < NOBS) {              // teacher forcing: s + (y - s)
                    float4 yA = *(const float4*)&data[((size_t)sbA * Ll + t) * NOBS + k0];
                    float4 yB = *(const float4*)&data[((size_t)sbB * Ll + t) * NOBS + k0];
                    float4 dA, dB;
                    dA.x = __fsub_rn(yA.x, a4.x); dA.y = __fsub_rn(yA.y, a4.y);
                    dA.z = __fsub_rn(yA.z, a4.z); dA.w = __fsub_rn(yA.w, a4.w);
                    dB.x = __fsub_rn(yB.x, b4.x); dB.y = __fsub_rn(yB.y, b4.y);
                    dB.z = __fsub_rn(yB.z, b4.z); dB.w = __fsub_rn(yB.w, b4.w);
                    if (nt == 0) {
                        size_t oA = ((size_t)sbA * Ll + t) * NOBS + k0;
                        size_t oB = ((size_t)sbB * Ll + t) * NOBS + k0;
                        *(float4*)&exps[oA] = a4;  *(float4*)&exps[oB] = b4;
                        *(float4*)&deltas[oA]   = dA; *(float4*)&deltas[oB]   = dB;
                        *(float4*)&partials[oA] = dA; *(float4*)&partials[oB] = dB;
                    }
                    a4.x = __fadd_rn(a4.x, dA.x); a4.y = __fadd_rn(a4.y, dA.y);
                    a4.z = __fadd_rn(a4.z, dA.z); a4.w = __fadd_rn(a4.w, dA.w);
                    b4.x = __fadd_rn(b4.x, dB.x); b4.y = __fadd_rn(b4.y, dB.y);
                    b4.z = __fadd_rn(b4.z, dB.z); b4.w = __fadd_rn(b4.w, dB.w);
                }
                u64* dst = &sx[(size_t)sp * SX_STRIDE + k0];
                ulonglong2 lo, hi;
                lo.x = pack2(a4.x, b4.x); lo.y = pack2(a4.y, b4.y);
                hi.x = pack2(a4.z, b4.z); hi.y = pack2(a4.w, b4.w);
                *(ulonglong2*)(dst)     = lo;
                *(ulonglong2*)(dst + 2) = hi;
            }
        }
        asm volatile("bar.sync %0, 128;" :: "r"(1 + e) : "memory");

        // -------- compute: 1 pair x 2 cols, ascending-k chains (bit-exact) ---
        u64 acc0 = 0, acc1 = 0;               // cols nA, nA+1 (both lanes 0.0f)
        #pragma unroll 16
        for (int k2 = 0; k2 < 256; k2++) {
            ulonglong2 X = *(const ulonglong2*)(xr + 2 * k2);      // x_k, x_k+1
            float4 a = *(const float4*)&sA2[(size_t)(k2 * 16 + cp) * 4];
            ffma2(acc0, pack2(a.x, a.x), X.x);   // col nA,   k
            ffma2(acc1, pack2(a.z, a.z), X.x);   // col nA+1, k
            ffma2(acc0, pack2(a.y, a.y), X.y);   // col nA,   k+1
            ffma2(acc1, pack2(a.w, a.w), X.y);   // col nA+1, k+1
        }

        float z0a, z0b, z1a, z1b;
        unpack2(acc0, z0a, z0b);              // (bA,nA), (bB,nA)
        unpack2(acc1, z1a, z1b);              // (bA,nA+1), (bB,nA+1)
        const float h00 = tanh_xla(z0a);
        const float h10 = tanh_xla(z1a);
        const float h01 = tanh_xla(z0b);
        const float h11 = tanh_xla(z1b);

        // states writes: per batch, cols (nA, nA+1) adjacent -> STG.64
        float* so = states + ((size_t)t + 1) * NHID + nA;
        *(float2*)(so + (size_t)bA * Ll * NHID) = make_float2(h00, h10);
        *(float2*)(so + (size_t)bB * Ll * NHID) = make_float2(h01, h11);

        if (t == NSTEPS - 1 && nt == 0) {     // nA, nA+1 < 32 here
            size_t oA = ((size_t)bA * Ll + (Ll - 1)) * NOBS + nA;
            size_t oB = ((size_t)bB * Ll + (Ll - 1)) * NOBS + nA;
            size_t dIA = ((size_t)bA * Ll + (Ll - 2)) * NOBS + nA;
            size_t dIB = ((size_t)bB * Ll + (Ll - 2)) * NOBS + nA;
            exps[oA] = h00; exps[oA + 1] = h10;
            exps[oB] = h01; exps[oB + 1] = h11;
            float dAx = __fsub_rn(data[dIA],     h00);
            float dAy = __fsub_rn(data[dIA + 1], h10);
            float dBx = __fsub_rn(data[dIB],     h01);
            float dBy = __fsub_rn(data[dIB + 1], h11);
            deltas[oA] = dAx; deltas[oA + 1] = dAy;
            deltas[oB] = dBx; deltas[oB + 1] = dBy;
            partials[oA] = dAx; partials[oA + 1] = dAy;
            partials[oB] = dBx; partials[oB + 1] = dBy;
        }

        if (t < NSTEPS - 1)
            engine_barrier(e, lt, ctr, base + (u64)(t + 1) * GRP_CTAS);
    }
}

// ---------------------------------------------------------------------------
extern "C" void kernel_launch(void* const* d_in, const int* in_sizes, int n_in,
                              void* d_out, int out_size) {
    const float* data = (const float*)d_in[0];  // [128,2048,32]
    const float* A    = (const float*)d_in[1];  // [512,512]
    const float* h0   = (const float*)d_in[2];  // [1,512]
    // d_in[3] = prob (0) -> dropout identity

    float* out      = (float*)d_out;
    float* exps     = out;
    float* states   = exps   + (size_t)Bb * Ll * NOBS;
    float* deltas   = states + (size_t)Bb * Ll * NHID;
    float* partials = deltas + (size_t)Bb * Ll * NOBS;

    cudaFuncSetAttribute(ptf_persistent,
                         cudaFuncAttributeMaxDynamicSharedMemorySize, SMEM_BYTES);
    ptf_persistent<<<NCTA, NTHREADS, SMEM_BYTES>>>(data, A, h0,
                                                   exps, states, deltas, partials);
}

// round 11
// speedup vs baseline: 1.0008x; 1.0008x over previous
#include <cuda_runtime.h>
#include <math.h>

#define Bb      128
#define Ll      2048
#define NOBS    32
#define NHID    512
#define NSTEPS  (Ll - 1)          // 2047
#define NCTA    64                // 16 n-tiles x 4 m-tiles
#define NTHREADS 256              // 2 engines x 128 threads
#define NBARS   (NSTEPS - 1)
typedef unsigned long long u64;
#define GRP_CTAS 16               // CTAs per (m-tile, engine) group
#define BARMOD  ((u64)NBARS * GRP_CTAS)

// SMEM: A interleaved [256 k2][16 cp][4 floats] + 2 x X pair-major [8][514] u64
#define SA2_FLOATS (256 * 16 * 4)               // 65536 B
#define SX_STRIDE  514                          // u64 rows (16B-aligned)
#define SX_U64     (8 * SX_STRIDE)
#define SMEM_BYTES (SA2_FLOATS * 4 + 2 * SX_U64 * 8)  // 65536 + 65792 = 131328 B

// per-(m-tile, engine) barrier counters, one 128B line each
__device__ u64 g_counts[4][2][16];

// ---------------------------------------------------------------------------
__device__ __forceinline__ u64 pack2(float a, float b) {
    u64 r;
    asm("mov.b64 %0, {%1, %2};" : "=l"(r) : "f"(a), "f"(b));
    return r;
}
__device__ __forceinline__ void unpack2(u64 v, float& a, float& b) {
    asm("mov.b64 {%0, %1}, %2;" : "=f"(a), "=f"(b) : "l"(v));
}
__device__ __forceinline__ void ffma2(u64& acc, u64 a, u64 x) {
    asm("fma.rn.f32x2 %0, %1, %2, %0;" : "+l"(acc) : "l"(a), "l"(x));
}

// XLA EmitFastTanh (fma path) — verified bit-exact (rel_err 0.0). DO NOT CHANGE.
__device__ __forceinline__ float tanh_xla(float x) {
    const float kClamp = 7.99881172180175781f;
    float xc = fminf(fmaxf(x, -kClamp), kClamp);
    float x2 = __fmul_rn(xc, xc);
    float num = -2.76076847742355e-16f;
    num = fmaf(x2, num, 2.00018790482477e-13f);
    num = fmaf(x2, num, -8.60467152213735e-11f);
    num = fmaf(x2, num, 5.12229709037114e-08f);
    num = fmaf(x2, num, 1.48572235717979e-05f);
    num = fmaf(x2, num, 6.37261928875436e-04f);
    num = fmaf(x2, num, 4.89352455891786e-03f);
    num = __fmul_rn(xc, num);
    float den = 1.19825839466702e-06f;
    den = fmaf(x2, den, 1.18534705686654e-04f);
    den = fmaf(x2, den, 2.26843463243900e-03f);
    den = fmaf(x2, den, 4.89352518554385e-03f);
    float r = __fdiv_rn(num, den);
    return (fabsf(x) < 0.0004f) ? x : r;
}

// engine barrier: named bar + release-arrive + acquire-poll, engine-scoped
__device__ __forceinline__ void engine_barrier(int eng, int lt, u64* ctr, u64 target) {
    asm volatile("bar.sync %0, 128;" :: "r"(1 + eng) : "memory");
    if (lt == 0) {
        asm volatile("red.global.release.gpu.add.u64 [%0], %1;"
                     :: "l"(ctr), "n"(1ULL) : "memory");
        u64 v;
        do {
            asm volatile("ld.global.acquire.gpu.u64 %0, [%1];"
                         : "=l"(v) : "l"(ctr));
        } while (v < target);
    }
    asm volatile("bar.sync %0, 128;" :: "r"(1 + eng) : "memory");
}

// ---------------------------------------------------------------------------
// Persistent HCNN scan, order-exact fp32, dual-engine latency hiding.
// 64 CTAs = 16 n-tiles (32 cols) x 4 m-tiles (32 batches).
// 256 threads = 2 engines x 128 threads. Engine e (warps 4e..4e+3, one warp
// per SMSP interleaved with the other engine's) runs an independent 16-batch
// recurrence: own sx buffer, own 16-CTA group barrier, named-bar sync.
// Compute per engine identical to R8: thread tile = 1 pair x 2 cols,
// full ascending-k f32x2 chains (bit-exact).
// ---------------------------------------------------------------------------
__global__ void __launch_bounds__(NTHREADS, 1) ptf_persistent(
    const float* __restrict__ data,   // [B, L, NOBS]
    const float* __restrict__ Amat,   // [NHID, NHID]
    const float* __restrict__ h0,     // [NHID]
    float* __restrict__ exps,
    float* __restrict__ states,       // doubles as the recurrent state
    float* __restrict__ deltas,
    float* __restrict__ partials)
{
    extern __shared__ char smem_raw[];
    float* sA2 = (float*)smem_raw;                        // [256][16][4]
    u64*   sxb = (u64*)(smem_raw + SA2_FLOATS * 4);       // [2][8][514]

    const int tid = threadIdx.x;
    const int e   = tid >> 7;                 // engine 0/1
    const int lt  = tid & 127;                // thread id within engine
    const int lw  = lt >> 5;                  // engine-local warp 0..3
    const int l   = lt & 31;
    const int nt  = blockIdx.x & 15;
    const int mt  = blockIdx.x >> 4;          // 0..3
    const int n0  = nt * 32;
    const int m0  = mt * 32 + e * 16;         // engine's 16-batch base
    u64* ctr = &g_counts[mt][e][0];
    u64* sx  = sxb + (size_t)e * SX_U64;

    // ---- barrier base (monotonic counter across graph replays) ----
    u64 base;
    {
        u64 v;
        asm volatile("ld.global.acquire.gpu.u64 %0, [%1];" : "=l"(v) : "l"(ctr));
        base = v - (v % BARMOD);
    }

    // ---- one-time: A -> sA2[k2][cp][4] = {a_n[2k2], a_n[2k2+1],
    //                                       a_n1[2k2], a_n1[2k2+1]} ----
    for (int i = tid; i < 256 * 16; i += NTHREADS) {
        const int k2 = i >> 4;           // 0..255
        const int cp = i & 15;           // 0..15
        const int n  = n0 + 2 * cp;
        float2 a0 = *(const float2*)&Amat[(size_t)n * NHID + 2 * k2];
        float2 a1 = *(const float2*)&Amat[(size_t)(n + 1) * NHID + 2 * k2];
        float4 v  = make_float4(a0.x, a0.y, a1.x, a1.y);
        *(float4*)&sA2[(size_t)i * 4] = v;
    }
    __syncthreads();    // last full-CTA sync; engines diverge after this

    // compute-thread identifiers (within engine)
    const int p   = lt & 7;                   // pair 0..7
    const int cp  = lt >> 3;                  // col-pair 0..15
    const int nA  = n0 + 2 * cp;              // cols nA, nA+1
    const int bA  = m0 + p;                   // batches bA, bA+8
    const int bB  = bA + 8;
    const u64* xr = sx + (size_t)p * SX_STRIDE;

    for (int t = 0; t < NSTEPS; t++) {
        // ---------------- stage state pairs (+ exact injection + outputs) ----
        // engine warp lw stages pairs lw and lw+4; 4 float4-chunks per pair
        #pragma unroll
        for (int r = 0; r < 2; r++) {
            const int sp  = lw + 4 * r;
            const int sbA = m0 + sp;
            const int sbB = sbA + 8;
            #pragma unroll
            for (int j = 0; j < 4; j++) {
                const int k0 = 4 * l + 128 * j;
                const float* srcA = (t == 0) ? (h0 + k0)
                                  : (states + ((size_t)sbA * Ll + t) * NHID + k0);
                const float* srcB = (t == 0) ? (h0 + k0)
                                  : (states + ((size_t)sbB * Ll + t) * NHID + k0);
                float4 a4 = *(const float4*)srcA;
                float4 b4 = *(const float4*)srcB;

                if (t == 0 && nt == 0) {      // states[:,0,:] = s0 (pre-inject)
                    *(float4*)&states[((size_t)sbA * Ll) * NHID + k0] = a4;
                    *(float4*)&states[((size_t)sbB * Ll) * NHID + k0] = b4;
                }
                if (k0 < NOBS) {              // teacher forcing: s + (y - s)
                    float4 yA = *(const float4*)&data[((size_t)sbA * Ll + t) * NOBS + k0];
                    float4 yB = *(const float4*)&data[((size_t)sbB * Ll + t) * NOBS + k0];
                    float4 dA, dB;
                    dA.x = __fsub_rn(yA.x, a4.x); dA.y = __fsub_rn(yA.y, a4.y);
                    dA.z = __fsub_rn(yA.z, a4.z); dA.w = __fsub_rn(yA.w, a4.w);
                    dB.x = __fsub_rn(yB.x, b4.x); dB.y = __fsub_rn(yB.y, b4.y);
                    dB.z = __fsub_rn(yB.z, b4.z); dB.w = __fsub_rn(yB.w, b4.w);
                    if (nt == 0) {
                        size_t oA = ((size_t)sbA * Ll + t) * NOBS + k0;
                        size_t oB = ((size_t)sbB * Ll + t) * NOBS + k0;
                        *(float4*)&exps[oA] = a4;  *(float4*)&exps[oB] = b4;
                        *(float4*)&deltas[oA]   = dA; *(float4*)&deltas[oB]   = dB;
                        *(float4*)&partials[oA] = dA; *(float4*)&partials[oB] = dB;
                    }
                    a4.x = __fadd_rn(a4.x, dA.x); a4.y = __fadd_rn(a4.y, dA.y);
                    a4.z = __fadd_rn(a4.z, dA.z); a4.w = __fadd_rn(a4.w, dA.w);
                    b4.x = __fadd_rn(b4.x, dB.x); b4.y = __fadd_rn(b4.y, dB.y);
                    b4.z = __fadd_rn(b4.z, dB.z); b4.w = __fadd_rn(b4.w, dB.w);
                }
                u64* dst = &sx[(size_t)sp * SX_STRIDE + k0];
                ulonglong2 lo, hi;
                lo.x = pack2(a4.x, b4.x); lo.y = pack2(a4.y, b4.y);
                hi.x = pack2(a4.z, b4.z); hi.y = pack2(a4.w, b4.w);
                *(ulonglong2*)(dst)     = lo;
                *(ulonglong2*)(dst + 2) = hi;
            }
        }
        asm volatile("bar.sync %0, 128;" :: "r"(1 + e) : "memory");

        // -------- compute: 1 pair x 2 cols, ascending-k chains (bit-exact) ---
        u64 acc0 = 0, acc1 = 0;               // cols nA, nA+1 (both lanes 0.0f)
        #pragma unroll 16
        for (int k2 = 0; k2 < 256; k2++) {
            ulonglong2 X = *(const ulonglong2*)(xr + 2 * k2);      // x_k, x_k+1
            float4 a = *(const float4*)&sA2[(size_t)(k2 * 16 + cp) * 4];
            ffma2(acc0, pack2(a.x, a.x), X.x);   // col nA,   k
            ffma2(acc1, pack2(a.z, a.z), X.x);   // col nA+1, k
            ffma2(acc0, pack2(a.y, a.y), X.y);   // col nA,   k+1
            ffma2(acc1, pack2(a.w, a.w), X.y);   // col nA+1, k+1
        }

        float z0a, z0b, z1a, z1b;
        unpack2(acc0, z0a, z0b);              // (bA,nA), (bB,nA)
        unpack2(acc1, z1a, z1b);              // (bA,nA+1), (bB,nA+1)
        const float h00 = tanh_xla(z0a);
        const float h10 = tanh_xla(z1a);
        const float h01 = tanh_xla(z0b);
        const float h11 = tanh_xla(z1b);

        // states writes: per batch, cols (nA, nA+1) adjacent -> STG.64
        float* so = states + ((size_t)t + 1) * NHID + nA;
        *(float2*)(so + (size_t)bA * Ll * NHID) = make_float2(h00, h10);
        *(float2*)(so + (size_t)bB * Ll * NHID) = make_float2(h01, h11);

        if (t == NSTEPS - 1 && nt == 0) {     // nA, nA+1 < 32 here
            size_t oA = ((size_t)bA * Ll + (Ll - 1)) * NOBS + nA;
            size_t oB = ((size_t)bB * Ll + (Ll - 1)) * NOBS + nA;
            size_t dIA = ((size_t)bA * Ll + (Ll - 2)) * NOBS + nA;
            size_t dIB = ((size_t)bB * Ll + (Ll - 2)) * NOBS + nA;
            exps[oA] = h00; exps[oA + 1] = h10;
            exps[oB] = h01; exps[oB + 1] = h11;
            float dAx = __fsub_rn(data[dIA],     h00);
            float dAy = __fsub_rn(data[dIA + 1], h10);
            float dBx = __fsub_rn(data[dIB],     h01);
            float dBy = __fsub_rn(data[dIB + 1], h11);
            deltas[oA] = dAx; deltas[oA + 1] = dAy;
            deltas[oB] = dBx; deltas[oB + 1] = dBy;
            partials[oA] = dAx; partials[oA + 1] = dAy;
            partials[oB] = dBx; partials[oB + 1] = dBy;
        }

        if (t < NSTEPS - 1)
            engine_barrier(e, lt, ctr, base + (u64)(t + 1) * GRP_CTAS);
    }
}

// ---------------------------------------------------------------------------
extern "C" void kernel_launch(void* const* d_in, const int* in_sizes, int n_in,
                              void* d_out, int out_size) {
    const float* data = (const float*)d_in[0];  // [128,2048,32]
    const float* A    = (const float*)d_in[1];  // [512,512]
    const float* h0   = (const float*)d_in[2];  // [1,512]
    // d_in[3] = prob (0) -> dropout identity

    float* out      = (float*)d_out;
    float* exps     = out;
    float* states   = exps   + (size_t)Bb * Ll * NOBS;
    float* deltas   = states + (size_t)Bb * Ll * NHID;
    float* partials = deltas + (size_t)Bb * Ll * NOBS;

    cudaFuncSetAttribute(ptf_persistent,
                         cudaFuncAttributeMaxDynamicSharedMemorySize, SMEM_BYTES);
    ptf_persistent<<<NCTA, NTHREADS, SMEM_BYTES>>>(data, A, h0,
                                                   exps, states, deltas, partials);
}

// round 12
// speedup vs baseline: 1.4103x; 1.4092x over previous
#include <cuda_runtime.h>
#include <math.h>

#define Bb      128
#define Ll      2048
#define NOBS    32
#define NHID    512
#define NSTEPS  (Ll - 1)          // 2047
#define NCTA    128
#define NTHREADS 128
typedef unsigned long long u64;
typedef unsigned int u32;
#define NBUMPS  ((u32)(NSTEPS - 1))   // 2046 flag bumps per producer per replay

// SMEM: A interleaved [256 k2][16 cp][4 floats] + 2 X chunk buffers
// X chunk buffer: 32 entries (2 k each) x 18 u64 (16 data + 2 pad) = 144B rows
#define SA2_FLOATS (256 * 16 * 4)              // 65536 B
#define XBUF_U64   (32 * 18)                   // 576 u64 = 4608 B
#define SMEM_BYTES (SA2_FLOATS * 4 + 2 * XBUF_U64 * 8)   // 74752 B

// per-(m-tile, n-tile) producer progress flags; one 128B line per mt row
__device__ __align__(128) u32 g_flags[8][32];

// ---------------------------------------------------------------------------
__device__ __forceinline__ u64 pack2(float a, float b) {
    u64 r;
    asm("mov.b64 %0, {%1, %2};" : "=l"(r) : "f"(a), "f"(b));
    return r;
}
__device__ __forceinline__ void unpack2(u64 v, float& a, float& b) {
    asm("mov.b64 {%0, %1}, %2;" : "=f"(a), "=f"(b) : "l"(v));
}
__device__ __forceinline__ void ffma2(u64& acc, u64 a, u64 x) {
    asm("fma.rn.f32x2 %0, %1, %2, %0;" : "+l"(acc) : "l"(a), "l"(x));
}
__device__ __forceinline__ u64 acq64(const u32* p) {
    u64 v;
    asm volatile("ld.global.acquire.gpu.u64 %0, [%1];" : "=l"(v) : "l"(p));
    return v;
}
__device__ __forceinline__ u32 acq32(const u32* p) {
    u32 v;
    asm volatile("ld.global.acquire.gpu.u32 %0, [%1];" : "=r"(v) : "l"(p));
    return v;
}

// XLA EmitFastTanh (fma path) — verified bit-exact (rel_err 0.0). DO NOT CHANGE.
__device__ __forceinline__ float tanh_xla(float x) {
    const float kClamp = 7.99881172180175781f;
    float xc = fminf(fmaxf(x, -kClamp), kClamp);
    float x2 = __fmul_rn(xc, xc);
    float num = -2.76076847742355e-16f;
    num = fmaf(x2, num, 2.00018790482477e-13f);
    num = fmaf(x2, num, -8.60467152213735e-11f);
    num = fmaf(x2, num, 5.12229709037114e-08f);
    num = fmaf(x2, num, 1.48572235717979e-05f);
    num = fmaf(x2, num, 6.37261928875436e-04f);
    num = fmaf(x2, num, 4.89352455891786e-03f);
    num = __fmul_rn(xc, num);
    float den = 1.19825839466702e-06f;
    den = fmaf(x2, den, 1.18534705686654e-04f);
    den = fmaf(x2, den, 2.26843463243900e-03f);
    den = fmaf(x2, den, 4.89352518554385e-03f);
    float r = __fdiv_rn(num, den);
    return (fabsf(x) < 0.0004f) ? x : r;
}

// ---------------------------------------------------------------------------
// Persistent HCNN scan, order-exact fp32, producer-flag chunked dataflow.
// 128 CTAs = 16 n-tiles (32 cols) x 8 m-tiles (16 batches = 8 pairs).
// No global/group barrier: producer (nt,mt) release-adds g_flags[mt][nt]
// after each step; consumers stage+consume k in 8 ascending 64-k chunks,
// chunk c gated on producers nt=2c,2c+1, polls+LDGs hidden under FMA halves.
// Compute tiling and arithmetic identical to the bit-exact R8 kernel.
// ---------------------------------------------------------------------------
__global__ void __launch_bounds__(NTHREADS, 1) ptf_persistent(
    const float* __restrict__ data,   // [B, L, NOBS]
    const float* __restrict__ Amat,   // [NHID, NHID]
    const float* __restrict__ h0,     // [NHID]
    float* __restrict__ exps,
    float* __restrict__ states,       // doubles as the recurrent state
    float* __restrict__ deltas,
    float* __restrict__ partials)
{
    extern __shared__ char smem_raw[];
    float* sA2 = (float*)smem_raw;                        // [256][16][4]
    u64*   sxb = (u64*)(smem_raw + SA2_FLOATS * 4);       // [2][32][18]

    const int tid = threadIdx.x;
    const int nt  = blockIdx.x & 15;
    const int mt  = blockIdx.x >> 4;
    const int n0  = nt * 32;
    const int m0  = mt * 16;
    const u32* flagrow = &g_flags[mt][0];
    u32* myflag = &g_flags[mt][nt];

    // flag base (monotonic across graph replays; all flags equal at launch)
    u32 base;
    {
        u32 v = acq32(myflag);
        base = v - (v % NBUMPS);
    }

    // ---- one-time: A -> sA2[k2][cp][4] = {a_n[2k2],a_n[2k2+1],a_n1[2k2],a_n1[2k2+1]}
    for (int i = tid; i < 256 * 16; i += NTHREADS) {
        const int k2 = i >> 4;
        const int cp = i & 15;
        const int n  = n0 + 2 * cp;
        float2 a0 = *(const float2*)&Amat[(size_t)n * NHID + 2 * k2];
        float2 a1 = *(const float2*)&Amat[(size_t)(n + 1) * NHID + 2 * k2];
        *(float4*)&sA2[(size_t)i * 4] = make_float4(a0.x, a0.y, a1.x, a1.y);
    }
    __syncthreads();

    // compute identifiers
    const int p   = tid & 7;                  // pair 0..7
    const int cp  = tid >> 3;                 // col-pair 0..15
    const int nA  = n0 + 2 * cp;              // cols nA, nA+1
    const int bA  = m0 + p;                   // batches bA, bA+8
    const int bB  = bA + 8;

    // staging identifiers
    const int sq  = tid & 15;                 // k-quad within 64-chunk (0..15)
    const int sp  = tid >> 4;                 // pair 0..7
    const int sbA = m0 + sp;
    const int sbB = sbA + 8;

    for (int t = 0; t < NSTEPS; t++) {
        const u32 Tt = base + (u32)t;          // required producer progress

        // ===== stage super-chunk 0 (k 0..63; includes injection/outputs) ====
        if (t > 0) {
            u64 fv = acq64(flagrow);           // flags nt=0,1
            while ((u32)fv < Tt || (u32)(fv >> 32) < Tt) fv = acq64(flagrow);
        }
        {
            const int kk = 4 * sq;             // 0..60
            float4 a4, b4;
            if (t == 0) {
                a4 = *(const float4*)(h0 + kk);
                b4 = a4;
                if (nt == 0) {                 // states[:,0,:] = s0 (pre-inject)
                    *(float4*)&states[((size_t)sbA * Ll) * NHID + kk] = a4;
                    *(float4*)&states[((size_t)sbB * Ll) * NHID + kk] = b4;
                }
            } else {
                a4 = *(const float4*)&states[((size_t)sbA * Ll + t) * NHID + kk];
                b4 = *(const float4*)&states[((size_t)sbB * Ll + t) * NHID + kk];
            }
            if (sq < 8) {                      // kk < 32: teacher forcing s+(y-s)
                float4 yA = *(const float4*)&data[((size_t)sbA * Ll + t) * NOBS + kk];
                float4 yB = *(const float4*)&data[((size_t)sbB * Ll + t) * NOBS + kk];
                float4 dA, dB;
                dA.x = __fsub_rn(yA.x, a4.x); dA.y = __fsub_rn(yA.y, a4.y);
                dA.z = __fsub_rn(yA.z, a4.z); dA.w = __fsub_rn(yA.w, a4.w);
                dB.x = __fsub_rn(yB.x, b4.x); dB.y = __fsub_rn(yB.y, b4.y);
                dB.z = __fsub_rn(yB.z, b4.z); dB.w = __fsub_rn(yB.w, b4.w);
                if (nt == 0) {
                    size_t oA = ((size_t)sbA * Ll + t) * NOBS + kk;
                    size_t oB = ((size_t)sbB * Ll + t) * NOBS + kk;
                    *(float4*)&exps[oA] = a4;  *(float4*)&exps[oB] = b4;
                    *(float4*)&deltas[oA]   = dA; *(float4*)&deltas[oB]   = dB;
                    *(float4*)&partials[oA] = dA; *(float4*)&partials[oB] = dB;
                }
                a4.x = __fadd_rn(a4.x, dA.x); a4.y = __fadd_rn(a4.y, dA.y);
                a4.z = __fadd_rn(a4.z, dA.z); a4.w = __fadd_rn(a4.w, dA.w);
                b4.x = __fadd_rn(b4.x, dB.x); b4.y = __fadd_rn(b4.y, dB.y);
                b4.z = __fadd_rn(b4.z, dB.z); b4.w = __fadd_rn(b4.w, dB.w);
            }
            u64* d = sxb + (size_t)(2 * sq) * 18 + 2 * sp;     // buffer 0
            ulonglong2 lo, hi;
            lo.x = pack2(a4.x, b4.x); lo.y = pack2(a4.y, b4.y);
            hi.x = pack2(a4.z, b4.z); hi.y = pack2(a4.w, b4.w);
            *(ulonglong2*)d        = lo;
            *(ulonglong2*)(d + 18) = hi;
        }
        __syncthreads();

        // ===== chunked compute with pipelined staging ========================
        u64 acc0 = 0, acc1 = 0;                // cols nA, nA+1 (both lanes 0.0f)
        #pragma unroll 1
        for (int sc = 0; sc < 8; sc++) {
            const u64* xb = sxb + (size_t)(sc & 1) * XBUF_U64;
            const int  scn = sc + 1;

            // early flag read for next chunk (latency hidden under half 1)
            u64 fv = 0;
            if (scn < 8 && t > 0) fv = acq64(flagrow + 2 * scn);

            // ---- compute half 1: entries 0..15 (k = 64sc .. 64sc+31) ----
            #pragma unroll
            for (int i = 0; i < 16; i++) {
                ulonglong2 X = *(const ulonglong2*)(xb + (size_t)i * 18 + 2 * p);
                float4 a = *(const float4*)&sA2[(size_t)(((sc * 32 + i) * 16) + cp) * 4];
                ffma2(acc0, pack2(a.x, a.x), X.x);
                ffma2(acc1, pack2(a.z, a.z), X.x);
                ffma2(acc0, pack2(a.y, a.y), X.y);
                ffma2(acc1, pack2(a.w, a.w), X.y);
            }

            float4 a4, b4;
            if (scn < 8) {
                if (t > 0) {
                    while ((u32)fv < Tt || (u32)(fv >> 32) < Tt)
                        fv = acq64(flagrow + 2 * scn);
                }
                const int kk = 64 * scn + 4 * sq;
                if (t == 0) {
                    a4 = *(const float4*)(h0 + kk);
                    b4 = a4;
                    if (nt == 0) {
                        *(float4*)&states[((size_t)sbA * Ll) * NHID + kk] = a4;
                        *(float4*)&states[((size_t)sbB * Ll) * NHID + kk] = b4;
                    }
                } else {
                    a4 = *(const float4*)&states[((size_t)sbA * Ll + t) * NHID + kk];
                    b4 = *(const float4*)&states[((size_t)sbB * Ll + t) * NHID + kk];
                }
            }

            // ---- compute half 2: entries 16..31 (staging LDG latency hides) --
            #pragma unroll
            for (int i = 16; i < 32; i++) {
                ulonglong2 X = *(const ulonglong2*)(xb + (size_t)i * 18 + 2 * p);
                float4 a = *(const float4*)&sA2[(size_t)(((sc * 32 + i) * 16) + cp) * 4];
                ffma2(acc0, pack2(a.x, a.x), X.x);
                ffma2(acc1, pack2(a.z, a.z), X.x);
                ffma2(acc0, pack2(a.y, a.y), X.y);
                ffma2(acc1, pack2(a.w, a.w), X.y);
            }

            if (scn < 8) {
                u64* d = sxb + (size_t)(scn & 1) * XBUF_U64
                             + (size_t)(2 * sq) * 18 + 2 * sp;
                ulonglong2 lo, hi;
                lo.x = pack2(a4.x, b4.x); lo.y = pack2(a4.y, b4.y);
                hi.x = pack2(a4.z, b4.z); hi.y = pack2(a4.w, b4.w);
                *(ulonglong2*)d        = lo;
                *(ulonglong2*)(d + 18) = hi;
                __syncthreads();
            }
        }

        // ===== tanh + writes =================================================
        float z0a, z0b, z1a, z1b;
        unpack2(acc0, z0a, z0b);              // (bA,nA), (bB,nA)
        unpack2(acc1, z1a, z1b);              // (bA,nA+1), (bB,nA+1)
        const float h00 = tanh_xla(z0a);
        const float h10 = tanh_xla(z1a);
        const float h01 = tanh_xla(z0b);
        const float h11 = tanh_xla(z1b);

        float* so = states + ((size_t)t + 1) * NHID + nA;
        *(float2*)(so + (size_t)bA * Ll * NHID) = make_float2(h00, h10);
        *(float2*)(so + (size_t)bB * Ll * NHID) = make_float2(h01, h11);

        if (t == NSTEPS - 1 && nt == 0) {     // nA, nA+1 < 32 here
            size_t oA = ((size_t)bA * Ll + (Ll - 1)) * NOBS + nA;
            size_t oB = ((size_t)bB * Ll + (Ll - 1)) * NOBS + nA;
            size_t dIA = ((size_t)bA * Ll + (Ll - 2)) * NOBS + nA;
            size_t dIB = ((size_t)bB * Ll + (Ll - 2)) * NOBS + nA;
            exps[oA] = h00; exps[oA + 1] = h10;
            exps[oB] = h01; exps[oB + 1] = h11;
            float dAx = __fsub_rn(data[dIA],     h00);
            float dAy = __fsub_rn(data[dIA + 1], h10);
            float dBx = __fsub_rn(data[dIB],     h01);
            float dBy = __fsub_rn(data[dIB + 1], h11);
            deltas[oA] = dAx; deltas[oA + 1] = dAy;
            deltas[oB] = dBx; deltas[oB + 1] = dBy;
            partials[oA] = dAx; partials[oA + 1] = dAy;
            partials[oB] = dBx; partials[oB + 1] = dBy;
        }

        // publish progress (2046 bumps per replay)
        if (t < NSTEPS - 1) {
            __syncthreads();                  // all threads' step writes issued
            if (tid == 0)
                asm volatile("red.global.release.gpu.add.u32 [%0], %1;"
                             :: "l"(myflag), "r"(1u) : "memory");
        }
    }
}

// ---------------------------------------------------------------------------
extern "C" void kernel_launch(void* const* d_in, const int* in_sizes, int n_in,
                              void* d_out, int out_size) {
    const float* data = (const float*)d_in[0];  // [128,2048,32]
    const float* A    = (const float*)d_in[1];  // [512,512]
    const float* h0   = (const float*)d_in[2];  // [1,512]
    // d_in[3] = prob (0) -> dropout identity

    float* out      = (float*)d_out;
    float* exps     = out;
    float* states   = exps   + (size_t)Bb * Ll * NOBS;
    float* deltas   = states + (size_t)Bb * Ll * NHID;
    float* partials = deltas + (size_t)Bb * Ll * NOBS;

    cudaFuncSetAttribute(ptf_persistent,
                         cudaFuncAttributeMaxDynamicSharedMemorySize, SMEM_BYTES);
    ptf_persistent<<<NCTA, NTHREADS, SMEM_BYTES>>>(data, A, h0,
                                                   exps, states, deltas, partials);
}

// round 13
// speedup vs baseline: 1.7393x; 1.2332x over previous
#include <cuda_runtime.h>
#include <math.h>

#define Bb      128
#define Ll      2048
#define NOBS    32
#define NHID    512
#define NSTEPS  (Ll - 1)          // 2047
#define NCTA    128
#define NTHREADS 128
typedef unsigned long long u64;
typedef unsigned int u32;
#define NBUMPS  ((u32)(NSTEPS - 1))   // 2046 bumps per warp per replay

// SMEM: A interleaved [256 k2][16 q][4 floats] + per-warp X [2 pairs][514] u64
#define SA2_FLOATS (256 * 16 * 4)               // 65536 B
#define SXW_U64    (2 * 514)                    // per-warp X region (8224 B)
#define SMEM_BYTES (SA2_FLOATS * 4 + 4 * SXW_U64 * 8)   // 98432 B

// per-(m-tile, warp, n-tile) producer flags; one 128B line per (mt,w)
__device__ __align__(128) u32 g_flags[8][4][32];

// ---------------------------------------------------------------------------
__device__ __forceinline__ u64 pack2(float a, float b) {
    u64 r;
    asm("mov.b64 %0, {%1, %2};" : "=l"(r) : "f"(a), "f"(b));
    return r;
}
__device__ __forceinline__ void unpack2(u64 v, float& a, float& b) {
    asm("mov.b64 {%0, %1}, %2;" : "=f"(a), "=f"(b) : "l"(v));
}
__device__ __forceinline__ void ffma2(u64& acc, u64 a, u64 x) {
    asm("fma.rn.f32x2 %0, %1, %2, %0;" : "+l"(acc) : "l"(a), "l"(x));
}
__device__ __forceinline__ u64 acq64(const u32* p) {
    u64 v;
    asm volatile("ld.global.acquire.gpu.u64 %0, [%1];" : "=l"(v) : "l"(p));
    return v;
}
__device__ __forceinline__ u32 acq32(const u32* p) {
    u32 v;
    asm volatile("ld.global.acquire.gpu.u32 %0, [%1];" : "=r"(v) : "l"(p));
    return v;
}
// spin until both u32 halves at f2 (8B-aligned) reach bt
__device__ __forceinline__ void wait2(const u32* f2, u32 bt) {
    u64 v = acq64(f2);
    while ((u32)v < bt || (u32)(v >> 32) < bt) v = acq64(f2);
}

// XLA EmitFastTanh (fma path) — verified bit-exact (rel_err 0.0). DO NOT CHANGE.
__device__ __forceinline__ float tanh_xla(float x) {
    const float kClamp = 7.99881172180175781f;
    float xc = fminf(fmaxf(x, -kClamp), kClamp);
    float x2 = __fmul_rn(xc, xc);
    float num = -2.76076847742355e-16f;
    num = fmaf(x2, num, 2.00018790482477e-13f);
    num = fmaf(x2, num, -8.60467152213735e-11f);
    num = fmaf(x2, num, 5.12229709037114e-08f);
    num = fmaf(x2, num, 1.48572235717979e-05f);
    num = fmaf(x2, num, 6.37261928875436e-04f);
    num = fmaf(x2, num, 4.89352455891786e-03f);
    num = __fmul_rn(xc, num);
    float den = 1.19825839466702e-06f;
    den = fmaf(x2, den, 1.18534705686654e-04f);
    den = fmaf(x2, den, 2.26843463243900e-03f);
    den = fmaf(x2, den, 4.89352518554385e-03f);
    float r = __fdiv_rn(num, den);
    return (fabsf(x) < 0.0004f) ? x : r;
}

// ---------------------------------------------------------------------------
// Persistent HCNN scan, order-exact fp32, WARP-AUTONOMOUS chunked dataflow.
// 128 CTAs = 16 n-tiles (32 cols) x 8 m-tiles. Warp w owns pairs {2w, 2w+1}:
// it stages them, computes them (lanes: p2 = l>>4 pair-half, q = l&15
// col-pair), and publishes g_flags[mt][w][nt] after each step. Consumers
// gate k-chunk c (64 k) on flags of (nt=2c, 2c+1) of the SAME (mt, w) —
// no __syncthreads in the main loop, only __syncwarp. LDG prefetch one
// chunk ahead hides staging; polls hide under FMA. Compute instruction
// sequence identical to the bit-exact R8 kernel (ascending-k chains).
// ---------------------------------------------------------------------------
__global__ void __launch_bounds__(NTHREADS, 1) ptf_persistent(
    const float* __restrict__ data,   // [B, L, NOBS]
    const float* __restrict__ Amat,   // [NHID, NHID]
    const float* __restrict__ h0,     // [NHID]
    float* __restrict__ exps,
    float* __restrict__ states,       // doubles as the recurrent state
    float* __restrict__ deltas,
    float* __restrict__ partials)
{
    extern __shared__ char smem_raw[];
    float* sA2   = (float*)smem_raw;                      // [256][16][4]
    u64*   sxall = (u64*)(smem_raw + SA2_FLOATS * 4);     // [4 warps][2][514]

    const int tid = threadIdx.x;
    const int w   = tid >> 5;
    const int l   = tid & 31;
    const int nt  = blockIdx.x & 15;
    const int mt  = blockIdx.x >> 4;
    const int n0  = nt * 32;
    const int m0  = mt * 16;

    const u32* flagrow = &g_flags[mt][w][0];
    u32* myflag = &g_flags[mt][w][nt];
    u32 base = acq32(myflag);
    base -= base % NBUMPS;                 // monotonic across graph replays

    // ---- one-time: A -> sA2[k2][q][4] = {a_n[2k2],a_n[2k2+1],a_n1[2k2],a_n1[2k2+1]}
    for (int i = tid; i < 256 * 16; i += NTHREADS) {
        const int k2 = i >> 4;
        const int q  = i & 15;
        const int n  = n0 + 2 * q;
        float2 a0 = *(const float2*)&Amat[(size_t)n * NHID + 2 * k2];
        float2 a1 = *(const float2*)&Amat[(size_t)(n + 1) * NHID + 2 * k2];
        *(float4*)&sA2[(size_t)i * 4] = make_float4(a0.x, a0.y, a1.x, a1.y);
    }
    __syncthreads();                       // only CTA-wide sync in the kernel

    // lane identifiers (staging and compute share the same mapping)
    const int p2 = l >> 4;                 // pair half 0/1
    const int q  = l & 15;                 // col-pair / k-quad index
    const int P  = 2 * w + p2;             // this lane's pair
    const int bA = m0 + P;                 // batches bA, bA+8
    const int bB = bA + 8;
    const int nA = n0 + 2 * q;             // compute cols nA, nA+1
    u64* xr = sxall + (size_t)w * SXW_U64 + (size_t)p2 * 514;

    for (int t = 0; t < NSTEPS; t++) {
        const u32 bt = base + (u32)t;

        // ---------- stage chunk 0 (k 0..63; includes injection/outputs) ------
        if (t > 0) wait2(flagrow, bt);     // producers nt=0,1
        {
            const int k0 = 4 * q;          // 0..60
            float4 fa, fb;
            if (t == 0) {
                fa = *(const float4*)(h0 + k0);
                fb = fa;
                if (nt == 0) {             // states[:,0,:] = s0 (pre-inject)
                    *(float4*)&states[((size_t)bA * Ll) * NHID + k0] = fa;
                    *(float4*)&states[((size_t)bB * Ll) * NHID + k0] = fb;
                }
            } else {
                fa = *(const float4*)&states[((size_t)bA * Ll + t) * NHID + k0];
                fb = *(const float4*)&states[((size_t)bB * Ll + t) * NHID + k0];
            }
            if (q < 8) {                   // k0 < 32: teacher forcing s + (y-s)
                float4 yA = *(const float4*)&data[((size_t)bA * Ll + t) * NOBS + k0];
                float4 yB = *(const float4*)&data[((size_t)bB * Ll + t) * NOBS + k0];
                float4 dA, dB;
                dA.x = __fsub_rn(yA.x, fa.x); dA.y = __fsub_rn(yA.y, fa.y);
                dA.z = __fsub_rn(yA.z, fa.z); dA.w = __fsub_rn(yA.w, fa.w);
                dB.x = __fsub_rn(yB.x, fb.x); dB.y = __fsub_rn(yB.y, fb.y);
                dB.z = __fsub_rn(yB.z, fb.z); dB.w = __fsub_rn(yB.w, fb.w);
                if (nt == 0) {
                    size_t oA = ((size_t)bA * Ll + t) * NOBS + k0;
                    size_t oB = ((size_t)bB * Ll + t) * NOBS + k0;
                    *(float4*)&exps[oA] = fa;  *(float4*)&exps[oB] = fb;
                    *(float4*)&deltas[oA]   = dA; *(float4*)&deltas[oB]   = dB;
                    *(float4*)&partials[oA] = dA; *(float4*)&partials[oB] = dB;
                }
                fa.x = __fadd_rn(fa.x, dA.x); fa.y = __fadd_rn(fa.y, dA.y);
                fa.z = __fadd_rn(fa.z, dA.z); fa.w = __fadd_rn(fa.w, dA.w);
                fb.x = __fadd_rn(fb.x, dB.x); fb.y = __fadd_rn(fb.y, dB.y);
                fb.z = __fadd_rn(fb.z, dB.z); fb.w = __fadd_rn(fb.w, dB.w);
            }
            u64* d = xr + k0;
            ulonglong2 lo, hi;
            lo.x = pack2(fa.x, fb.x); lo.y = pack2(fa.y, fb.y);
            hi.x = pack2(fa.z, fb.z); hi.y = pack2(fa.w, fb.w);
            *(ulonglong2*)(d)     = lo;
            *(ulonglong2*)(d + 2) = hi;
        }
        __syncwarp();

        // ---------- chunked compute, prefetch next chunk under FMA -----------
        u64 acc0 = 0, acc1 = 0;            // cols nA, nA+1 (both lanes 0.0f)
        #pragma unroll 1
        for (int c = 0; c < 8; c++) {
            float4 ga, gb;
            const bool more = (c < 7);
            if (more) {                    // poll + LDG chunk c+1 (hidden)
                if (t > 0) wait2(flagrow + 2 * (c + 1), bt);
                const int kn = 64 * (c + 1) + 4 * q;
                if (t == 0) {
                    ga = *(const float4*)(h0 + kn);
                    gb = ga;
                    if (nt == 0) {
                        *(float4*)&states[((size_t)bA * Ll) * NHID + kn] = ga;
                        *(float4*)&states[((size_t)bB * Ll) * NHID + kn] = gb;
                    }
                } else {
                    ga = *(const float4*)&states[((size_t)bA * Ll + t) * NHID + kn];
                    gb = *(const float4*)&states[((size_t)bB * Ll + t) * NHID + kn];
                }
            }

            // compute chunk c: k2 in [32c, 32c+32), ascending (bit-exact)
            const u64*   xc = xr + 64 * c;
            const float* ac = sA2 + ((size_t)(32 * c * 16) + q) * 4;
            #pragma unroll
            for (int j = 0; j < 32; j++) {
                ulonglong2 X = *(const ulonglong2*)(xc + 2 * j);
                float4 a = *(const float4*)(ac + (size_t)j * 64);
                ffma2(acc0, pack2(a.x, a.x), X.x);
                ffma2(acc1, pack2(a.z, a.z), X.x);
                ffma2(acc0, pack2(a.y, a.y), X.y);
                ffma2(acc1, pack2(a.w, a.w), X.y);
            }

            if (more) {                    // stage chunk c+1 (no injection: k>=64)
                u64* d = xr + 64 * (c + 1) + 4 * q;
                ulonglong2 lo, hi;
                lo.x = pack2(ga.x, gb.x); lo.y = pack2(ga.y, gb.y);
                hi.x = pack2(ga.z, gb.z); hi.y = pack2(ga.w, gb.w);
                *(ulonglong2*)(d)     = lo;
                *(ulonglong2*)(d + 2) = hi;
                __syncwarp();
            }
        }

        // ---------- tanh + writes -------------------------------------------
        float z0a, z0b, z1a, z1b;
        unpack2(acc0, z0a, z0b);           // (bA,nA), (bB,nA)
        unpack2(acc1, z1a, z1b);           // (bA,nA+1), (bB,nA+1)
        const float h00 = tanh_xla(z0a);
        const float h10 = tanh_xla(z1a);
        const float h01 = tanh_xla(z0b);
        const float h11 = tanh_xla(z1b);

        float* so = states + ((size_t)t + 1) * NHID + nA;
        *(float2*)(so + (size_t)bA * Ll * NHID) = make_float2(h00, h10);
        *(float2*)(so + (size_t)bB * Ll * NHID) = make_float2(h01, h11);

        if (t == NSTEPS - 1 && nt == 0) {  // nA, nA+1 < 32 here
            size_t oA = ((size_t)bA * Ll + (Ll - 1)) * NOBS + nA;
            size_t oB = ((size_t)bB * Ll + (Ll - 1)) * NOBS + nA;
            size_t dIA = ((size_t)bA * Ll + (Ll - 2)) * NOBS + nA;
            size_t dIB = ((size_t)bB * Ll + (Ll - 2)) * NOBS + nA;
            exps[oA] = h00; exps[oA + 1] = h10;
            exps[oB] = h01; exps[oB + 1] = h11;
            float dAx = __fsub_rn(data[dIA],     h00);
            float dAy = __fsub_rn(data[dIA + 1], h10);
            float dBx = __fsub_rn(data[dIB],     h01);
            float dBy = __fsub_rn(data[dIB + 1], h11);
            deltas[oA] = dAx; deltas[oA + 1] = dAy;
            deltas[oB] = dBx; deltas[oB + 1] = dBy;
            partials[oA] = dAx; partials[oA + 1] = dAy;
            partials[oB] = dBx; partials[oB + 1] = dBy;
        }

        // ---------- publish this warp's progress ----------------------------
        if (t < NSTEPS - 1) {
            __syncwarp();                  // order all lanes' STGs (warp fence)
            if (l == 0)
                asm volatile("red.global.release.gpu.add.u32 [%0], %1;"
                             :: "l"(myflag), "r"(1u) : "memory");
        }
    }
}

// ---------------------------------------------------------------------------
extern "C" void kernel_launch(void* const* d_in, const int* in_sizes, int n_in,
                              void* d_out, int out_size) {
    const float* data = (const float*)d_in[0];  // [128,2048,32]
    const float* A    = (const float*)d_in[1];  // [512,512]
    const float* h0   = (const float*)d_in[2];  // [1,512]
    // d_in[3] = prob (0) -> dropout identity

    float* out      = (float*)d_out;
    float* exps     = out;
    float* states   = exps   + (size_t)Bb * Ll * NOBS;
    float* deltas   = states + (size_t)Bb * Ll * NHID;
    float* partials = deltas + (size_t)Bb * Ll * NOBS;

    cudaFuncSetAttribute(ptf_persistent,
                         cudaFuncAttributeMaxDynamicSharedMemorySize, SMEM_BYTES);
    ptf_persistent<<<NCTA, NTHREADS, SMEM_BYTES>>>(data, A, h0,
                                                   exps, states, deltas, partials);
}